// round 2
// baseline (speedup 1.0000x reference)
#include <cuda_runtime.h>
#include <cstdint>

// Harmonic lattice potential:
//   inputs: pos (N,3) f32, edge_index (2,E) int32 (JAX demotes i64->i32),
//           batch (N,) int32 (sorted)
//   outputs: energy (64,) f32  ++  forces (N,3) f32   (concatenated in d_out)
//
// Strategy:
//   - forces accumulated into float4-padded __device__ scratch via
//     red.global.add.v4.f32 (one vector reduction per edge endpoint instead
//     of 3 scalar atomics) -- scratch lives in L2 (1.6 MB).
//   - energy privatized into 64 shared-memory bins per CTA, flushed once.
//   - finalize kernel writes coalesced forces + energy into d_out.

#define KSPRING 1.0f
#define R0 1.0f
#define EPSF 1e-20f
#define NUM_GRAPHS 64
#define MAX_N 131072

__device__ float4 g_fscratch[MAX_N];
__device__ float  g_escratch[NUM_GRAPHS];

__device__ __forceinline__ void red_add_v4(float4* addr, float a, float b, float c, float d) {
    asm volatile("red.global.add.v4.f32 [%0], {%1, %2, %3, %4};"
                 :: "l"(addr), "f"(a), "f"(b), "f"(c), "f"(d)
                 : "memory");
}

__global__ void zero_kernel(int N) {
    int t = blockIdx.x * blockDim.x + threadIdx.x;
    if (t < N) g_fscratch[t] = make_float4(0.f, 0.f, 0.f, 0.f);
    if (t < NUM_GRAPHS) g_escratch[t] = 0.f;
}

__global__ void edge_kernel(const float* __restrict__ pos,
                            const int* __restrict__ ei,
                            const int* __restrict__ batch,
                            int E) {
    __shared__ float ebins[NUM_GRAPHS];
    int t = threadIdx.x;
    if (t < NUM_GRAPHS) ebins[t] = 0.f;
    __syncthreads();

    int stride = gridDim.x * blockDim.x;
    for (int e = blockIdx.x * blockDim.x + t; e < E; e += stride) {
        int i = __ldg(&ei[e]);
        int j = __ldg(&ei[E + e]);

        float xi = __ldg(&pos[3 * i + 0]);
        float yi = __ldg(&pos[3 * i + 1]);
        float zi = __ldg(&pos[3 * i + 2]);
        float xj = __ldg(&pos[3 * j + 0]);
        float yj = __ldg(&pos[3 * j + 1]);
        float zj = __ldg(&pos[3 * j + 2]);
        int gi = __ldg(&batch[i]);

        float dx = xi - xj;
        float dy = yi - yj;
        float dz = zi - zj;
        float dd = dx * dx + dy * dy + dz * dz;
        float d  = sqrtf(dd);
        float delta = d - R0;

        // energy contribution
        atomicAdd(&ebins[gi], 0.5f * KSPRING * delta * delta);

        // force: f = K*delta * dr/(d+eps);  i gets -f, j gets +f
        float s = (KSPRING * delta) / (d + EPSF);
        float fx = s * dx, fy = s * dy, fz = s * dz;

        red_add_v4(&g_fscratch[i], -fx, -fy, -fz, 0.f);
        red_add_v4(&g_fscratch[j],  fx,  fy,  fz, 0.f);
    }

    __syncthreads();
    if (t < NUM_GRAPHS) atomicAdd(&g_escratch[t], ebins[t]);
}

__global__ void finalize_kernel(float* __restrict__ out, int N) {
    int t = blockIdx.x * blockDim.x + threadIdx.x;
    int total = 3 * N;
    if (t < total) {
        int node = t / 3;
        int c    = t - 3 * node;
        out[NUM_GRAPHS + t] = ((const float*)g_fscratch)[node * 4 + c];
    }
    if (t < NUM_GRAPHS) out[t] = g_escratch[t];
}

extern "C" void kernel_launch(void* const* d_in, const int* in_sizes, int n_in,
                              void* d_out, int out_size) {
    const float* pos   = (const float*)d_in[0];
    const int*   ei    = (const int*)d_in[1];
    const int*   batch = (const int*)d_in[2];
    float* out = (float*)d_out;

    int N = in_sizes[0] / 3;
    int E = in_sizes[1] / 2;

    {
        int threads = 256;
        int blocks  = (N + threads - 1) / threads;
        zero_kernel<<<blocks, threads>>>(N);
    }
    {
        int threads = 256;
        // 4 edges per thread nominal; grid-stride handles remainder
        int blocks = (E + threads * 4 - 1) / (threads * 4);
        edge_kernel<<<blocks, threads>>>(pos, ei, batch, E);
    }
    {
        int threads = 256;
        int blocks  = (3 * N + threads - 1) / threads;
        finalize_kernel<<<blocks, threads>>>(out, N);
    }
}

// round 3
// speedup vs baseline: 1.1729x; 1.1729x over previous
#include <cuda_runtime.h>
#include <cstdint>

// Harmonic lattice potential — R2
//   inputs: pos (N,3) f32, edge_index (2,E) int32, batch (N,) int32 (sorted)
//   output: energy (64,) f32 ++ forces (N,3) f32
//
// R2 changes vs R1 (78.6us):
//   - pos packed to float4 in prep kernel -> 1 LDG.128 per endpoint gather
//     (was 3 scalar LDG, 3 L1tex wavefronts each).
//   - per-edge energy rides the unused .w lane of the i-endpoint
//     red.global.add.v4.f32; finalize bins node .w by (sorted) batch.
//     Deletes per-edge batch gather + 3.2M shared atomics.
//   - edge indices loaded as int4 (4 edges/thread), gathers batched for MLP,
//     red asm has no "memory" clobber so loads can be hoisted across it.

#define R0 1.0f
#define EPSF 1e-20f
#define NUM_GRAPHS 64
#define MAXN 131072

__device__ float4 g_acc[MAXN];    // force.xyz + energy.w accumulator
__device__ float4 g_pos4[MAXN];   // packed positions

__device__ __forceinline__ void red_add_v4(float4* addr, float a, float b, float c, float d) {
    asm volatile("red.global.add.v4.f32 [%0], {%1, %2, %3, %4};"
                 :: "l"(addr), "f"(a), "f"(b), "f"(c), "f"(d));
}

__global__ void prep_kernel(const float* __restrict__ pos, float* __restrict__ out, int N) {
    int t = blockIdx.x * blockDim.x + threadIdx.x;
    if (t < N) {
        g_acc[t] = make_float4(0.f, 0.f, 0.f, 0.f);
        g_pos4[t] = make_float4(pos[3 * t], pos[3 * t + 1], pos[3 * t + 2], 0.f);
    }
    if (t < NUM_GRAPHS) out[t] = 0.f;   // zero energy slots (d_out poisoned)
}

// Vector path: requires E % 4 == 0 (holds for E = 3.2M). Q = E/4 quads.
__global__ void edge_vec_kernel(const int4* __restrict__ ia,
                                const int4* __restrict__ ja,
                                int Q) {
    int stride = gridDim.x * blockDim.x;
    for (int q = blockIdx.x * blockDim.x + threadIdx.x; q < Q; q += stride) {
        int4 iv = __ldg(&ia[q]);
        int4 jv = __ldg(&ja[q]);
        int is[4] = {iv.x, iv.y, iv.z, iv.w};
        int js[4] = {jv.x, jv.y, jv.z, jv.w};

        float4 pi[4], pj[4];
#pragma unroll
        for (int k = 0; k < 4; k++) {
            pi[k] = __ldg(&g_pos4[is[k]]);
            pj[k] = __ldg(&g_pos4[js[k]]);
        }

#pragma unroll
        for (int k = 0; k < 4; k++) {
            float dx = pi[k].x - pj[k].x;
            float dy = pi[k].y - pj[k].y;
            float dz = pi[k].z - pj[k].z;
            float dd = fmaf(dx, dx, fmaf(dy, dy, dz * dz));
            float d  = sqrtf(dd);
            float delta = d - R0;             // K = 1
            float e = 0.5f * delta * delta;
            float s = delta / (d + EPSF);
            float fx = s * dx, fy = s * dy, fz = s * dz;

            red_add_v4(&g_acc[is[k]], -fx, -fy, -fz, e);
            red_add_v4(&g_acc[js[k]],  fx,  fy,  fz, 0.f);
        }
    }
}

// Scalar fallback (E % 4 != 0 — not expected for this dataset).
__global__ void edge_scalar_kernel(const int* __restrict__ ei, int E) {
    int stride = gridDim.x * blockDim.x;
    for (int e = blockIdx.x * blockDim.x + threadIdx.x; e < E; e += stride) {
        int i = __ldg(&ei[e]);
        int j = __ldg(&ei[E + e]);
        float4 pi = __ldg(&g_pos4[i]);
        float4 pj = __ldg(&g_pos4[j]);
        float dx = pi.x - pj.x, dy = pi.y - pj.y, dz = pi.z - pj.z;
        float dd = fmaf(dx, dx, fmaf(dy, dy, dz * dz));
        float d  = sqrtf(dd);
        float delta = d - R0;
        float e2 = 0.5f * delta * delta;
        float s = delta / (d + EPSF);
        float fx = s * dx, fy = s * dy, fz = s * dz;
        red_add_v4(&g_acc[i], -fx, -fy, -fz, e2);
        red_add_v4(&g_acc[j],  fx,  fy,  fz, 0.f);
    }
}

__global__ void finalize_kernel(float* __restrict__ out,
                                const int* __restrict__ batch, int N) {
    __shared__ float ebins[NUM_GRAPHS];
    int t = threadIdx.x;
    if (t < NUM_GRAPHS) ebins[t] = 0.f;
    __syncthreads();

    int n = blockIdx.x * blockDim.x + t;
    if (n < N) {
        float4 a = g_acc[n];
        out[NUM_GRAPHS + 3 * n + 0] = a.x;
        out[NUM_GRAPHS + 3 * n + 1] = a.y;
        out[NUM_GRAPHS + 3 * n + 2] = a.z;
        atomicAdd(&ebins[__ldg(&batch[n])], a.w);   // sorted batch: near-uniform bin per block
    }
    __syncthreads();
    if (t < NUM_GRAPHS) {
        float v = ebins[t];
        if (v != 0.f) atomicAdd(&out[t], v);
    }
}

extern "C" void kernel_launch(void* const* d_in, const int* in_sizes, int n_in,
                              void* d_out, int out_size) {
    const float* pos   = (const float*)d_in[0];
    const int*   ei    = (const int*)d_in[1];
    const int*   batch = (const int*)d_in[2];
    float* out = (float*)d_out;

    int N = in_sizes[0] / 3;
    int E = in_sizes[1] / 2;

    {
        int threads = 256;
        int blocks  = (N + threads - 1) / threads;
        prep_kernel<<<blocks, threads>>>(pos, out, N);
    }
    if ((E & 3) == 0) {
        int Q = E >> 2;
        int threads = 256;
        int blocks = 1184;                       // 8 CTAs/SM x 148 SMs, grid-stride
        int needed = (Q + threads - 1) / threads;
        if (blocks > needed) blocks = needed;
        edge_vec_kernel<<<blocks, threads>>>((const int4*)ei, (const int4*)(ei + E), Q);
    } else {
        int threads = 256;
        int blocks = 1184;
        int needed = (E + threads - 1) / threads;
        if (blocks > needed) blocks = needed;
        edge_scalar_kernel<<<blocks, threads>>>(ei, E);
    }
    {
        int threads = 256;
        int blocks  = (N + threads - 1) / threads;
        finalize_kernel<<<blocks, threads>>>(out, batch, N);
    }
}

// round 4
// speedup vs baseline: 1.3071x; 1.1144x over previous
#include <cuda_runtime.h>
#include <cstdint>

// Harmonic lattice potential — R3
//   inputs: pos (N,3) f32, edge_index (2,E) int32, batch (N,) int32 (sorted)
//   output: energy (64,) f32 ++ forces (N,3) f32
//
// R3 changes vs R2 (67.0us):
//   - exact-fit grid (no grid-stride): 1 quad (4 edges)/thread, all loads
//     front-batched by ptxas for max MLP.
//   - rsqrt math: no FDIV/sqrt; guards i==j edges via fmax(dd, 1e-40).
//   - prep kernel: 128-thread blocks for better SM spread (was grid-limited).

#define R0 1.0f
#define NUM_GRAPHS 64
#define MAXN 131072

__device__ float4 g_acc[MAXN];    // force.xyz + energy.w accumulator
__device__ float4 g_pos4[MAXN];   // packed positions

__device__ __forceinline__ void red_add_v4(float4* addr, float a, float b, float c, float d) {
    asm volatile("red.global.add.v4.f32 [%0], {%1, %2, %3, %4};"
                 :: "l"(addr), "f"(a), "f"(b), "f"(c), "f"(d));
}

__global__ void prep_kernel(const float* __restrict__ pos, float* __restrict__ out, int N) {
    int t = blockIdx.x * blockDim.x + threadIdx.x;
    if (t < N) {
        g_acc[t]  = make_float4(0.f, 0.f, 0.f, 0.f);
        g_pos4[t] = make_float4(__ldg(&pos[3 * t]), __ldg(&pos[3 * t + 1]),
                                __ldg(&pos[3 * t + 2]), 0.f);
    }
    if (t < NUM_GRAPHS) out[t] = 0.f;   // zero energy slots (d_out poisoned)
}

// Vector path: E % 4 == 0. One quad (4 edges) per thread, exact grid.
__global__ void __launch_bounds__(256)
edge_vec_kernel(const int4* __restrict__ ia, const int4* __restrict__ ja, int Q) {
    int q = blockIdx.x * blockDim.x + threadIdx.x;
    if (q >= Q) return;

    int4 iv = __ldg(&ia[q]);
    int4 jv = __ldg(&ja[q]);
    int is[4] = {iv.x, iv.y, iv.z, iv.w};
    int js[4] = {jv.x, jv.y, jv.z, jv.w};

    float4 pi[4], pj[4];
#pragma unroll
    for (int k = 0; k < 4; k++) {
        pi[k] = __ldg(&g_pos4[is[k]]);
        pj[k] = __ldg(&g_pos4[js[k]]);
    }

#pragma unroll
    for (int k = 0; k < 4; k++) {
        float dx = pi[k].x - pj[k].x;
        float dy = pi[k].y - pj[k].y;
        float dz = pi[k].z - pj[k].z;
        float dd = fmaf(dx, dx, fmaf(dy, dy, dz * dz));
        float rinv = rsqrtf(fmaxf(dd, 1e-40f));
        float d = dd * rinv;                  // = sqrt(dd); exact 0 when dd==0
        float delta = d - R0;                 // K = 1
        float e = 0.5f * delta * delta;
        float s = delta * rinv;               // ~ delta/(d+eps); dx==0 when dd==0
        float fx = s * dx, fy = s * dy, fz = s * dz;

        red_add_v4(&g_acc[is[k]], -fx, -fy, -fz, e);
        red_add_v4(&g_acc[js[k]],  fx,  fy,  fz, 0.f);
    }
}

// Scalar fallback (E % 4 != 0 — not expected for this dataset).
__global__ void edge_scalar_kernel(const int* __restrict__ ei, int E) {
    int e = blockIdx.x * blockDim.x + threadIdx.x;
    if (e >= E) return;
    int i = __ldg(&ei[e]);
    int j = __ldg(&ei[E + e]);
    float4 pi = __ldg(&g_pos4[i]);
    float4 pj = __ldg(&g_pos4[j]);
    float dx = pi.x - pj.x, dy = pi.y - pj.y, dz = pi.z - pj.z;
    float dd = fmaf(dx, dx, fmaf(dy, dy, dz * dz));
    float rinv = rsqrtf(fmaxf(dd, 1e-40f));
    float d = dd * rinv;
    float delta = d - R0;
    float e2 = 0.5f * delta * delta;
    float s = delta * rinv;
    float fx = s * dx, fy = s * dy, fz = s * dz;
    red_add_v4(&g_acc[i], -fx, -fy, -fz, e2);
    red_add_v4(&g_acc[j],  fx,  fy,  fz, 0.f);
}

__global__ void finalize_kernel(float* __restrict__ out,
                                const int* __restrict__ batch, int N) {
    __shared__ float ebins[NUM_GRAPHS];
    int t = threadIdx.x;
    if (t < NUM_GRAPHS) ebins[t] = 0.f;
    __syncthreads();

    int n = blockIdx.x * blockDim.x + t;
    if (n < N) {
        float4 a = g_acc[n];
        out[NUM_GRAPHS + 3 * n + 0] = a.x;
        out[NUM_GRAPHS + 3 * n + 1] = a.y;
        out[NUM_GRAPHS + 3 * n + 2] = a.z;
        atomicAdd(&ebins[__ldg(&batch[n])], a.w);   // sorted batch: near-uniform bin per block
    }
    __syncthreads();
    if (t < NUM_GRAPHS) {
        float v = ebins[t];
        if (v != 0.f) atomicAdd(&out[t], v);
    }
}

extern "C" void kernel_launch(void* const* d_in, const int* in_sizes, int n_in,
                              void* d_out, int out_size) {
    const float* pos   = (const float*)d_in[0];
    const int*   ei    = (const int*)d_in[1];
    const int*   batch = (const int*)d_in[2];
    float* out = (float*)d_out;

    int N = in_sizes[0] / 3;
    int E = in_sizes[1] / 2;

    {
        int threads = 128;
        int blocks  = (N + threads - 1) / threads;
        prep_kernel<<<blocks, threads>>>(pos, out, N);
    }
    if ((E & 3) == 0) {
        int Q = E >> 2;
        int threads = 256;
        int blocks  = (Q + threads - 1) / threads;
        edge_vec_kernel<<<blocks, threads>>>((const int4*)ei, (const int4*)(ei + E), Q);
    } else {
        int threads = 256;
        int blocks  = (E + threads - 1) / threads;
        edge_scalar_kernel<<<blocks, threads>>>(ei, E);
    }
    {
        int threads = 128;
        int blocks  = (N + threads - 1) / threads;
        finalize_kernel<<<blocks, threads>>>(out, batch, N);
    }
}